// round 16
// baseline (speedup 1.0000x reference)
#include <cuda_runtime.h>

typedef unsigned int u32;
typedef unsigned long long u64;
typedef unsigned short u16;

#define NSEG 2621440u      // voxels per sample == template size
#define NSAMP 8
#define SEGS 9             // 8 samples + 1 template
#define TPB 256
#define IPT 16
#define TILE 4096          // TPB*IPT
#define TILES 640          // NSEG / TILE (exact)
#define BINS 2048          // 11-bit digits

// Static device scratch
__device__ u64 g_bufA[(size_t)SEGS * NSEG];                 // single intermediate buffer
__device__ u32 g_th[2ull * SEGS * TILES * BINS];            // [plane][seg][tile][digit] (tile-major)
__device__ u32 g_ghist[2 * SEGS * BINS];                    // global digit hist per (plane,seg)
__device__ u32 g_gbase[2 * SEGS * BINS];                    // exclusive scan of g_ghist
__device__ float g_tval[NSEG];                              // sorted template values

__device__ __forceinline__ u32 f2k(float f) {
    u32 u = __float_as_uint(f);
    return u ^ ((u & 0x80000000u) ? 0xFFFFFFFFu : 0x80000000u);
}
__device__ __forceinline__ float k2f(u32 u) {
    u ^= ((u & 0x80000000u) ? 0x80000000u : 0xFFFFFFFFu);
    return __uint_as_float(u);
}

// ---------------- zero global hists ----------------
__global__ void zero_k() {
    u32 i = blockIdx.x * blockDim.x + threadIdx.x;
    if (i < 2 * SEGS * BINS) g_ghist[i] = 0;
}

// ---------------- read floats: global hists (both planes) + plane-0 per-tile hist ----------------
// plane 0 digit = key bits [10:21) (mantissa -> uniform, plain atomics)
// plane 1 digit = key bits [21:32) (exp+sign -> skewed, warp-aggregated)
__global__ void __launch_bounds__(TPB) pack_hist_k(const float* __restrict__ x,
                                                   const float* __restrict__ t) {
    __shared__ u32 h[2 * BINS];   // 16 KB
    const int tid = threadIdx.x;
    const int l = tid & 31;
    const int seg = blockIdx.y;
    const int tile = blockIdx.x;
    for (int i = tid; i < 2 * BINS; i += TPB) h[i] = 0;
    __syncthreads();

    const float* src = (seg < NSAMP) ? (x + (size_t)seg * NSEG) : t;
    const u32 base = tile * TILE;
    #pragma unroll
    for (int k = 0; k < 4; k++) {
        u32 j = base + (u32)(k * TPB * 4) + tid * 4;
        float4 v = *reinterpret_cast<const float4*>(src + j);
        u32 kk[4] = { f2k(v.x), f2k(v.y), f2k(v.z), f2k(v.w) };
        #pragma unroll
        for (int e = 0; e < 4; e++) {
            atomicAdd(&h[(kk[e] >> 10) & (BINS - 1)], 1u);      // plane 0
            u32 d1 = kk[e] >> 21;                               // plane 1 (skewed)
            u32 m1 = __match_any_sync(0xFFFFFFFFu, d1);
            if ((int)(__ffs(m1) - 1) == l) atomicAdd(&h[BINS + d1], (u32)__popc(m1));
        }
    }
    __syncthreads();
    // global hists (both planes)
    for (int i = tid; i < 2 * BINS; i += TPB) {
        u32 c = h[i];
        if (c) {
            int p = (i >= BINS);
            atomicAdd(&g_ghist[(p * SEGS + seg) * BINS + (i & (BINS - 1))], c);
        }
    }
    // plane-0 per-tile hist (tile-major -> coalesced)
    const size_t thb = ((size_t)(0 * SEGS + seg) * TILES + tile) * BINS;
    for (int d = tid; d < BINS; d += TPB) g_th[thb + d] = h[d];
}

// ---------------- plane-1 per-tile hist over u64 items in A (key = hi u32) ----------------
__global__ void __launch_bounds__(TPB) hist1_k() {
    __shared__ u32 h[2][BINS];   // 16 KB, two copies to spread atomics
    const u32* __restrict__ in = reinterpret_cast<const u32*>(g_bufA);
    const int t = threadIdx.x;
    const int w = t >> 5;
    const int l = t & 31;
    const int tile = blockIdx.x, seg = blockIdx.y;
    for (int i = t; i < 2 * BINS; i += TPB) (&h[0][0])[i] = 0;
    __syncthreads();
    const size_t base = 2 * ((size_t)seg * NSEG + (size_t)tile * TILE) + 1;
    #pragma unroll
    for (int k = 0; k < IPT; k++) {
        u32 key = __ldcs(&in[base + 2 * (size_t)(k * TPB + t)]);
        u32 d = key >> 21;                      // skewed -> aggregate
        u32 m = __match_any_sync(0xFFFFFFFFu, d);
        if ((int)(__ffs(m) - 1) == l) atomicAdd(&h[w & 1][d], (u32)__popc(m));
    }
    __syncthreads();
    const size_t thb = ((size_t)(1 * SEGS + seg) * TILES + tile) * BINS;
    for (int d = t; d < BINS; d += TPB) g_th[thb + d] = h[0][d] + h[1][d];
}

// ---------------- per-(plane,seg) exclusive digit scan over 2048 bins ----------------
__global__ void __launch_bounds__(256) gscan_k() {
    __shared__ u32 wsum[8];
    const int seg = blockIdx.x, p = blockIdx.y;
    const int t = threadIdx.x, l = t & 31, w = t >> 5;
    const u32 base = (u32)(p * SEGS + seg) * BINS + t * 8;
    u32 v[8];
    #pragma unroll
    for (int i = 0; i < 8; i++) v[i] = g_ghist[base + i];
    u32 tot = 0;
    #pragma unroll
    for (int i = 0; i < 8; i++) { u32 c = v[i]; v[i] = tot; tot += c; }
    u32 sc = tot;
    #pragma unroll
    for (int off = 1; off < 32; off <<= 1) {
        u32 n = __shfl_up_sync(0xFFFFFFFFu, sc, off);
        if (l >= off) sc += n;
    }
    if (l == 31) wsum[w] = sc;
    __syncthreads();
    if (t == 0) {
        u32 run = 0;
        #pragma unroll
        for (int i = 0; i < 8; i++) { u32 c = wsum[i]; wsum[i] = run; run += c; }
    }
    __syncthreads();
    u32 ebase = wsum[w] + sc - tot;
    #pragma unroll
    for (int i = 0; i < 8; i++) g_gbase[base + i] = ebase + v[i];
}

// ---------------- tile scan, tile-major layout, digit-parallel (coalesced, high MLP) ----------------
// thread = one digit; block = 256 contiguous digits; loop over tiles.
__global__ void __launch_bounds__(256) tscan_k(int P) {
    const int seg = blockIdx.x;
    const u32 d = blockIdx.y * 256u + threadIdx.x;
    u32 run = g_gbase[(u32)(P * SEGS + seg) * BINS + d];
    const size_t base = ((size_t)(P * SEGS + seg) * TILES) * BINS + d;
    #pragma unroll 4
    for (int tile = 0; tile < TILES; tile++) {
        size_t a = base + (size_t)tile * BINS;
        u32 v = g_th[a];
        g_th[a] = run;
        run += v;
    }
}

// ======================================================================
// 2048-bin scatter engine (R10 ranking, correctness-proven):
// warp-major item order j = w*512 + k*32 + l; per-(digit, warp-pair) packed
// u16 counters bumped atomically by round leaders (old value = warp prefix);
// 4-word cross-warp scan per digit; pos = delta[d] + warpbase + prefix.
// ======================================================================

// ---------------- pass 0: floats -> u64 records in A (digit = bits[10:21)) ----------------
__global__ void __launch_bounds__(TPB, 3) scatter0_k(const float* __restrict__ x,
                                                     const float* __restrict__ bv) {
    __shared__ u32 pc[BINS * 4];     // 32 KB packed u16 halves: word = [digit][warp-pair]
    __shared__ u32 delta[BINS];      // 8 KB absolute digit base for this tile

    const int t = threadIdx.x;
    const int w = t >> 5;
    const int l = t & 31;
    const u32 lmlt = (1u << l) - 1u;
    const int pairo = w >> 1;
    const u32 sh16 = (u32)(w & 1) * 16;
    const u32 tile = blockIdx.x;
    const int seg = blockIdx.y;

    const float* __restrict__ src = (seg < NSAMP) ? (x + (size_t)seg * NSEG) : bv;
    const size_t sbase = (size_t)seg * NSEG;

    #pragma unroll
    for (int i = 0; i < (BINS * 4) / TPB; i++) pc[i * TPB + t] = 0;
    const size_t thb = ((size_t)(0 * SEGS + seg) * TILES + tile) * BINS;
    #pragma unroll
    for (int i = 0; i < BINS / TPB; i++) delta[i * TPB + t] = g_th[thb + (u32)i * TPB + t];
    __syncthreads();

    const u32 jb = tile * TILE + (u32)w * 512 + l;   // + k*32
    u32 key[IPT];
    #pragma unroll
    for (int k = 0; k < IPT; k++) key[k] = f2k(__ldcs(&src[jb + (u32)k * 32]));

    u16 pp[IPT];
    #pragma unroll
    for (int k = 0; k < IPT; k++) {
        u32 d = (key[k] >> 10) & (BINS - 1);
        u32 m = __match_any_sync(0xFFFFFFFFu, d);
        int leader = (int)(__ffs(m) - 1);
        u32 r = __popc(m & lmlt);
        u32 old = 0;
        if (l == leader)
            old = (atomicAdd(&pc[d * 4 + pairo], (u32)__popc(m) << sh16) >> sh16) & 0xFFFFu;
        old = __shfl_sync(0xFFFFFFFFu, old, leader);
        pp[k] = (u16)(old + r);
    }
    __syncthreads();

    // cross-warp exclusive scan per digit (8 digits per thread)
    #pragma unroll
    for (int i = 0; i < BINS / TPB; i++) {
        u32 d = (u32)i * TPB + t;
        u32 run = 0;
        #pragma unroll
        for (int p = 0; p < 4; p++) {
            u32 wd = pc[d * 4 + p];
            u32 c0 = wd & 0xFFFFu, c1 = wd >> 16;
            pc[d * 4 + p] = run | ((run + c0) << 16);
            run += c0 + c1;
        }
    }
    __syncthreads();

    #pragma unroll
    for (int k = 0; k < IPT; k++) {
        u32 d = (key[k] >> 10) & (BINS - 1);
        u32 wb = (pc[d * 4 + pairo] >> sh16) & 0xFFFFu;
        u32 pos = delta[d] + wb + (u32)pp[k];
        g_bufA[sbase + pos] = ((u64)key[k] << 32) | (jb + (u32)k * 32);
    }
}

// ---------------- pass 1: A -> final (digit = bits[21:32)) ----------------
// MODE 1: out[idx] = g_tval[pos]   (samples)
// MODE 2: g_tval[pos] = key-as-float (template)
template<int MODE>
__global__ void __launch_bounds__(TPB, 3) scatter1_k(float* __restrict__ outf, int segOff) {
    __shared__ u32 pc[BINS * 4];     // 32 KB
    __shared__ u32 delta[BINS];      // 8 KB

    const int t = threadIdx.x;
    const int w = t >> 5;
    const int l = t & 31;
    const u32 lmlt = (1u << l) - 1u;
    const int pairo = w >> 1;
    const u32 sh16 = (u32)(w & 1) * 16;
    const u32 tile = blockIdx.x;
    const int seg = blockIdx.y + segOff;
    const size_t sbase = (size_t)seg * NSEG;

    #pragma unroll
    for (int i = 0; i < (BINS * 4) / TPB; i++) pc[i * TPB + t] = 0;
    const size_t thb = ((size_t)(1 * SEGS + seg) * TILES + tile) * BINS;
    #pragma unroll
    for (int i = 0; i < BINS / TPB; i++) delta[i * TPB + t] = g_th[thb + (u32)i * TPB + t];
    __syncthreads();

    const size_t base = sbase + (size_t)tile * TILE + (u32)w * 512 + l;   // + k*32
    u64 item[IPT];
    #pragma unroll
    for (int k = 0; k < IPT; k++) item[k] = __ldcs(&g_bufA[base + (u32)k * 32]);

    u16 pp[IPT];
    #pragma unroll
    for (int k = 0; k < IPT; k++) {
        u32 d = (u32)(item[k] >> 53);   // key bits [21:32) = item bits [53:64)
        u32 m = __match_any_sync(0xFFFFFFFFu, d);
        int leader = (int)(__ffs(m) - 1);
        u32 r = __popc(m & lmlt);
        u32 old = 0;
        if (l == leader)
            old = (atomicAdd(&pc[d * 4 + pairo], (u32)__popc(m) << sh16) >> sh16) & 0xFFFFu;
        old = __shfl_sync(0xFFFFFFFFu, old, leader);
        pp[k] = (u16)(old + r);
    }
    __syncthreads();

    #pragma unroll
    for (int i = 0; i < BINS / TPB; i++) {
        u32 d = (u32)i * TPB + t;
        u32 run = 0;
        #pragma unroll
        for (int p = 0; p < 4; p++) {
            u32 wd = pc[d * 4 + p];
            u32 c0 = wd & 0xFFFFu, c1 = wd >> 16;
            pc[d * 4 + p] = run | ((run + c0) << 16);
            run += c0 + c1;
        }
    }
    __syncthreads();

    #pragma unroll
    for (int k = 0; k < IPT; k++) {
        u32 d = (u32)(item[k] >> 53);
        u32 wb = (pc[d * 4 + pairo] >> sh16) & 0xFFFFu;
        u32 pos = delta[d] + wb + (u32)pp[k];
        if (MODE == 2) {
            g_tval[pos] = k2f((u32)(item[k] >> 32));
        } else {
            outf[sbase + (u32)item[k]] = __ldg(&g_tval[pos]);
        }
    }
}

extern "C" void kernel_launch(void* const* d_in, const int* in_sizes, int n_in,
                              void* d_out, int out_size) {
    const float* x  = (const float*)d_in[0];
    const float* bv = (const float*)d_in[1];
    float* out = (float*)d_out;

    zero_k<<<144, 256>>>();
    pack_hist_k<<<dim3(TILES, SEGS), TPB>>>(x, bv);
    gscan_k<<<dim3(SEGS, 2), 256>>>();

    // pass 0: key bits [10:21)   floats -> A
    tscan_k<<<dim3(SEGS, BINS / 256), 256>>>(0);
    scatter0_k<<<dim3(TILES, SEGS), TPB>>>(x, bv);

    // pass 1: key bits [21:32)   A -> final
    hist1_k<<<dim3(TILES, SEGS), TPB>>>();
    tscan_k<<<dim3(SEGS, BINS / 256), 256>>>(1);
    scatter1_k<2><<<dim3(TILES, 1), TPB>>>(nullptr, NSAMP);   // template -> g_tval
    scatter1_k<1><<<dim3(TILES, NSAMP), TPB>>>(out, 0);       // fused epilogue
}

// round 17
// speedup vs baseline: 1.1447x; 1.1447x over previous
#include <cuda_runtime.h>

typedef unsigned int u32;
typedef unsigned long long u64;
typedef unsigned short u16;

#define NSEG 2621440u      // voxels per sample == template size
#define NSAMP 8
#define SEGS 9             // 8 samples + 1 template
#define TPB 256
#define IPT 16
#define TILE 4096          // TPB*IPT
#define TILES 640          // NSEG / TILE (exact)
#define BINS 2048          // 11-bit digits

// Static device scratch
__device__ u64 g_bufA[(size_t)SEGS * NSEG];                 // single intermediate buffer
__device__ u32 g_th[2ull * SEGS * BINS * TILES];            // [plane][seg][digit][tile] (digit-major)
__device__ u32 g_ghist[2 * SEGS * BINS];                    // global digit hist per (plane,seg)
__device__ u32 g_gbase[2 * SEGS * BINS];                    // exclusive scan of g_ghist
__device__ float g_tval[NSEG];                              // sorted template values

__device__ __forceinline__ u32 f2k(float f) {
    u32 u = __float_as_uint(f);
    return u ^ ((u & 0x80000000u) ? 0xFFFFFFFFu : 0x80000000u);
}
__device__ __forceinline__ float k2f(u32 u) {
    u ^= ((u & 0x80000000u) ? 0x80000000u : 0xFFFFFFFFu);
    return __uint_as_float(u);
}

// ---------------- zero global hists ----------------
__global__ void zero_k() {
    u32 i = blockIdx.x * blockDim.x + threadIdx.x;
    if (i < 2 * SEGS * BINS) g_ghist[i] = 0;
}

// ---------------- read floats: global hists (both planes) + plane-0 per-tile hist ----------------
// plane 0 digit = key bits [10:21) (mantissa -> uniform, plain atomics)
// plane 1 digit = key bits [21:32) (exp+sign -> skewed, warp-aggregated)
__global__ void __launch_bounds__(TPB) pack_hist_k(const float* __restrict__ x,
                                                   const float* __restrict__ t) {
    __shared__ u32 h[2 * BINS];   // 16 KB
    const int tid = threadIdx.x;
    const int l = tid & 31;
    const int seg = blockIdx.y;
    const int tile = blockIdx.x;
    for (int i = tid; i < 2 * BINS; i += TPB) h[i] = 0;
    __syncthreads();

    const float* src = (seg < NSAMP) ? (x + (size_t)seg * NSEG) : t;
    const u32 base = tile * TILE;
    #pragma unroll
    for (int k = 0; k < 4; k++) {
        u32 j = base + (u32)(k * TPB * 4) + tid * 4;
        float4 v = *reinterpret_cast<const float4*>(src + j);
        u32 kk[4] = { f2k(v.x), f2k(v.y), f2k(v.z), f2k(v.w) };
        #pragma unroll
        for (int e = 0; e < 4; e++) {
            atomicAdd(&h[(kk[e] >> 10) & (BINS - 1)], 1u);      // plane 0
            u32 d1 = kk[e] >> 21;                               // plane 1 (skewed)
            u32 m1 = __match_any_sync(0xFFFFFFFFu, d1);
            if ((int)(__ffs(m1) - 1) == l) atomicAdd(&h[BINS + d1], (u32)__popc(m1));
        }
    }
    __syncthreads();
    // global hists (both planes)
    for (int i = tid; i < 2 * BINS; i += TPB) {
        u32 c = h[i];
        if (c) {
            int p = (i >= BINS);
            atomicAdd(&g_ghist[(p * SEGS + seg) * BINS + (i & (BINS - 1))], c);
        }
    }
    // plane-0 per-tile hist (digit-major: row per digit, element = tile)
    const size_t thb = (size_t)(0 * SEGS + seg) * BINS * TILES;
    for (int d = tid; d < BINS; d += TPB)
        g_th[thb + (size_t)d * TILES + tile] = h[d];
}

// ---------------- plane-1 per-tile hist over u64 items in A (key = hi u32) ----------------
__global__ void __launch_bounds__(TPB) hist1_k() {
    __shared__ u32 h[2][BINS];   // 16 KB, two copies to spread atomics
    const u32* __restrict__ in = reinterpret_cast<const u32*>(g_bufA);
    const int t = threadIdx.x;
    const int w = t >> 5;
    const int l = t & 31;
    const int tile = blockIdx.x, seg = blockIdx.y;
    for (int i = t; i < 2 * BINS; i += TPB) (&h[0][0])[i] = 0;
    __syncthreads();
    const size_t base = 2 * ((size_t)seg * NSEG + (size_t)tile * TILE) + 1;
    #pragma unroll
    for (int k = 0; k < IPT; k++) {
        u32 key = __ldcs(&in[base + 2 * (size_t)(k * TPB + t)]);
        u32 d = key >> 21;                      // skewed -> aggregate
        u32 m = __match_any_sync(0xFFFFFFFFu, d);
        if ((int)(__ffs(m) - 1) == l) atomicAdd(&h[w & 1][d], (u32)__popc(m));
    }
    __syncthreads();
    const size_t thb = (size_t)(1 * SEGS + seg) * BINS * TILES;
    for (int d = t; d < BINS; d += TPB)
        g_th[thb + (size_t)d * TILES + tile] = h[0][d] + h[1][d];
}

// ---------------- per-(plane,seg) exclusive digit scan over 2048 bins ----------------
__global__ void __launch_bounds__(256) gscan_k() {
    __shared__ u32 wsum[8];
    const int seg = blockIdx.x, p = blockIdx.y;
    const int t = threadIdx.x, l = t & 31, w = t >> 5;
    const u32 base = (u32)(p * SEGS + seg) * BINS + t * 8;
    u32 v[8];
    #pragma unroll
    for (int i = 0; i < 8; i++) v[i] = g_ghist[base + i];
    u32 tot = 0;
    #pragma unroll
    for (int i = 0; i < 8; i++) { u32 c = v[i]; v[i] = tot; tot += c; }
    u32 sc = tot;
    #pragma unroll
    for (int off = 1; off < 32; off <<= 1) {
        u32 n = __shfl_up_sync(0xFFFFFFFFu, sc, off);
        if (l >= off) sc += n;
    }
    if (l == 31) wsum[w] = sc;
    __syncthreads();
    if (t == 0) {
        u32 run = 0;
        #pragma unroll
        for (int i = 0; i < 8; i++) { u32 c = wsum[i]; wsum[i] = run; run += c; }
    }
    __syncthreads();
    u32 ebase = wsum[w] + sc - tot;
    #pragma unroll
    for (int i = 0; i < 8; i++) g_gbase[base + i] = ebase + v[i];
}

// ---------------- per-(seg,digit) scan over tiles (R13 engine: warp per digit row) ----------------
// grid (SEGS, BINS/8), 256 threads = 8 warps; warp owns one contiguous 640-word row
__global__ void __launch_bounds__(256) tscan_k(int P) {
    const int seg = blockIdx.x;
    const int t = threadIdx.x, w = t >> 5, l = t & 31;
    const int d = blockIdx.y * 8 + w;
    u32* row = g_th + ((size_t)(P * SEGS + seg) * BINS + d) * TILES;
    u32 run = g_gbase[(u32)(P * SEGS + seg) * BINS + d];
    for (int c = 0; c < TILES; c += 32) {
        u32 v = row[c + l];
        u32 s = v;
        #pragma unroll
        for (int off = 1; off < 32; off <<= 1) {
            u32 n = __shfl_up_sync(0xFFFFFFFFu, s, off);
            if (l >= off) s += n;
        }
        row[c + l] = run + s - v;          // exclusive absolute offset
        run += __shfl_sync(0xFFFFFFFFu, s, 31);
    }
}

// ======================================================================
// 2048-bin scatter engine (R10 ranking, correctness-proven):
// warp-major item order j = w*512 + k*32 + l; per-(digit, warp-pair) packed
// u16 counters bumped atomically by round leaders (old value = warp prefix);
// 4-word cross-warp scan per digit; pos = delta[d] + warpbase + prefix.
// ======================================================================

// ---------------- pass 0: floats -> u64 records in A (digit = bits[10:21)) ----------------
__global__ void __launch_bounds__(TPB, 3) scatter0_k(const float* __restrict__ x,
                                                     const float* __restrict__ bv) {
    __shared__ u32 pc[BINS * 4];     // 32 KB packed u16 halves: word = [digit][warp-pair]
    __shared__ u32 delta[BINS];      // 8 KB absolute digit base for this tile

    const int t = threadIdx.x;
    const int w = t >> 5;
    const int l = t & 31;
    const u32 lmlt = (1u << l) - 1u;
    const int pairo = w >> 1;
    const u32 sh16 = (u32)(w & 1) * 16;
    const u32 tile = blockIdx.x;
    const int seg = blockIdx.y;

    const float* __restrict__ src = (seg < NSAMP) ? (x + (size_t)seg * NSEG) : bv;
    const size_t sbase = (size_t)seg * NSEG;

    #pragma unroll
    for (int i = 0; i < (BINS * 4) / TPB; i++) pc[i * TPB + t] = 0;
    const size_t thb = (size_t)(0 * SEGS + seg) * BINS * TILES;
    #pragma unroll
    for (int i = 0; i < BINS / TPB; i++) {
        u32 d = (u32)i * TPB + t;
        delta[d] = g_th[thb + (size_t)d * TILES + tile];
    }
    __syncthreads();

    const u32 jb = tile * TILE + (u32)w * 512 + l;   // + k*32
    u32 key[IPT];
    #pragma unroll
    for (int k = 0; k < IPT; k++) key[k] = f2k(__ldcs(&src[jb + (u32)k * 32]));

    u16 pp[IPT];
    #pragma unroll
    for (int k = 0; k < IPT; k++) {
        u32 d = (key[k] >> 10) & (BINS - 1);
        u32 m = __match_any_sync(0xFFFFFFFFu, d);
        int leader = (int)(__ffs(m) - 1);
        u32 r = __popc(m & lmlt);
        u32 old = 0;
        if (l == leader)
            old = (atomicAdd(&pc[d * 4 + pairo], (u32)__popc(m) << sh16) >> sh16) & 0xFFFFu;
        old = __shfl_sync(0xFFFFFFFFu, old, leader);
        pp[k] = (u16)(old + r);
    }
    __syncthreads();

    // cross-warp exclusive scan per digit (8 digits per thread)
    #pragma unroll
    for (int i = 0; i < BINS / TPB; i++) {
        u32 d = (u32)i * TPB + t;
        u32 run = 0;
        #pragma unroll
        for (int p = 0; p < 4; p++) {
            u32 wd = pc[d * 4 + p];
            u32 c0 = wd & 0xFFFFu, c1 = wd >> 16;
            pc[d * 4 + p] = run | ((run + c0) << 16);
            run += c0 + c1;
        }
    }
    __syncthreads();

    #pragma unroll
    for (int k = 0; k < IPT; k++) {
        u32 d = (key[k] >> 10) & (BINS - 1);
        u32 wb = (pc[d * 4 + pairo] >> sh16) & 0xFFFFu;
        u32 pos = delta[d] + wb + (u32)pp[k];
        g_bufA[sbase + pos] = ((u64)key[k] << 32) | (jb + (u32)k * 32);
    }
}

// ---------------- pass 1: A -> final (digit = bits[21:32)) ----------------
// MODE 1: out[idx] = g_tval[pos]   (samples)
// MODE 2: g_tval[pos] = key-as-float (template)
template<int MODE>
__global__ void __launch_bounds__(TPB, 3) scatter1_k(float* __restrict__ outf, int segOff) {
    __shared__ u32 pc[BINS * 4];     // 32 KB
    __shared__ u32 delta[BINS];      // 8 KB

    const int t = threadIdx.x;
    const int w = t >> 5;
    const int l = t & 31;
    const u32 lmlt = (1u << l) - 1u;
    const int pairo = w >> 1;
    const u32 sh16 = (u32)(w & 1) * 16;
    const u32 tile = blockIdx.x;
    const int seg = blockIdx.y + segOff;
    const size_t sbase = (size_t)seg * NSEG;

    #pragma unroll
    for (int i = 0; i < (BINS * 4) / TPB; i++) pc[i * TPB + t] = 0;
    const size_t thb = (size_t)(1 * SEGS + seg) * BINS * TILES;
    #pragma unroll
    for (int i = 0; i < BINS / TPB; i++) {
        u32 d = (u32)i * TPB + t;
        delta[d] = g_th[thb + (size_t)d * TILES + tile];
    }
    __syncthreads();

    const size_t base = sbase + (size_t)tile * TILE + (u32)w * 512 + l;   // + k*32
    u64 item[IPT];
    #pragma unroll
    for (int k = 0; k < IPT; k++) item[k] = __ldcs(&g_bufA[base + (u32)k * 32]);

    u16 pp[IPT];
    #pragma unroll
    for (int k = 0; k < IPT; k++) {
        u32 d = (u32)(item[k] >> 53);   // key bits [21:32) = item bits [53:64)
        u32 m = __match_any_sync(0xFFFFFFFFu, d);
        int leader = (int)(__ffs(m) - 1);
        u32 r = __popc(m & lmlt);
        u32 old = 0;
        if (l == leader)
            old = (atomicAdd(&pc[d * 4 + pairo], (u32)__popc(m) << sh16) >> sh16) & 0xFFFFu;
        old = __shfl_sync(0xFFFFFFFFu, old, leader);
        pp[k] = (u16)(old + r);
    }
    __syncthreads();

    #pragma unroll
    for (int i = 0; i < BINS / TPB; i++) {
        u32 d = (u32)i * TPB + t;
        u32 run = 0;
        #pragma unroll
        for (int p = 0; p < 4; p++) {
            u32 wd = pc[d * 4 + p];
            u32 c0 = wd & 0xFFFFu, c1 = wd >> 16;
            pc[d * 4 + p] = run | ((run + c0) << 16);
            run += c0 + c1;
        }
    }
    __syncthreads();

    #pragma unroll
    for (int k = 0; k < IPT; k++) {
        u32 d = (u32)(item[k] >> 53);
        u32 wb = (pc[d * 4 + pairo] >> sh16) & 0xFFFFu;
        u32 pos = delta[d] + wb + (u32)pp[k];
        if (MODE == 2) {
            g_tval[pos] = k2f((u32)(item[k] >> 32));
        } else {
            outf[sbase + (u32)item[k]] = __ldg(&g_tval[pos]);
        }
    }
}

extern "C" void kernel_launch(void* const* d_in, const int* in_sizes, int n_in,
                              void* d_out, int out_size) {
    const float* x  = (const float*)d_in[0];
    const float* bv = (const float*)d_in[1];
    float* out = (float*)d_out;

    zero_k<<<144, 256>>>();
    pack_hist_k<<<dim3(TILES, SEGS), TPB>>>(x, bv);
    gscan_k<<<dim3(SEGS, 2), 256>>>();

    // pass 0: key bits [10:21)   floats -> A
    tscan_k<<<dim3(SEGS, BINS / 8), 256>>>(0);
    scatter0_k<<<dim3(TILES, SEGS), TPB>>>(x, bv);

    // pass 1: key bits [21:32)   A -> final
    hist1_k<<<dim3(TILES, SEGS), TPB>>>();
    tscan_k<<<dim3(SEGS, BINS / 8), 256>>>(1);
    scatter1_k<2><<<dim3(TILES, 1), TPB>>>(nullptr, NSAMP);   // template -> g_tval
    scatter1_k<1><<<dim3(TILES, NSAMP), TPB>>>(out, 0);       // fused epilogue
}